// round 12
// baseline (speedup 1.0000x reference)
#include <cuda_runtime.h>
#include <cuda_bf16.h>
#include <math.h>
#include <float.h>

#define HW    65536
#define CIN   512
#define HALF  256
#define NUM   64
#define NPP   1024
#define W_IMG 256
#define KP    72     // Ps pitch (floats)
#define KBRP  80     // interleaved big/res pitch (u32)
#define VTP   72     // Vt pitch (floats)

// scratch (device globals: allocation-free rule)
__device__ float    g_q[NUM * NPP * HALF];    // (pn, ch) q, scaled
__device__ float    g_kp[HALF * NUM];         // (ch, patch) pooled k
__device__ float    g_vp[NUM * HALF];         // (patch, ch) pooled v
__device__ unsigned g_abr[NUM * NPP * 64];    // attn bf16 big/res interleaved blocks
__device__ float    g_avt[NUM * NPP * NUM];   // attn tf32, [p][jt][d][perm(jl)]
__device__ float    g_mid[NUM * NPP * HALF];  // (pn, ch) attention output
__device__ float    g_pscale[1280];
__device__ float    g_pbias[1280];

// ---------------------------------------------------------------------------
__device__ __forceinline__ float t32(float x) {
    asm("cvt.rna.tf32.f32 %0, %0;" : "+f"(x));
    return x;
}
// pack two fp32 into bf16x2: lo = first k element, hi = second
__device__ __forceinline__ unsigned pbf(float lo, float hi) {
    unsigned r;
    asm("cvt.rn.bf16x2.f32 %0, %2, %1;" : "=r"(r) : "f"(lo), "f"(hi));
    return r;
}
__device__ __forceinline__ void mma8(float* d,
    unsigned a0, unsigned a1, unsigned a2, unsigned a3,
    unsigned b0, unsigned b1)
{
    asm volatile(
        "mma.sync.aligned.m16n8k8.row.col.f32.tf32.tf32.f32 "
        "{%0,%1,%2,%3},{%4,%5,%6,%7},{%8,%9},{%0,%1,%2,%3};"
        : "+f"(d[0]), "+f"(d[1]), "+f"(d[2]), "+f"(d[3])
        : "r"(a0), "r"(a1), "r"(a2), "r"(a3), "r"(b0), "r"(b1));
}
__device__ __forceinline__ void mmabf(float* d,
    unsigned a0, unsigned a1, unsigned a2, unsigned a3,
    unsigned b0, unsigned b1)
{
    asm volatile(
        "mma.sync.aligned.m16n8k16.row.col.f32.bf16.bf16.f32 "
        "{%0,%1,%2,%3},{%4,%5,%6,%7},{%8,%9},{%0,%1,%2,%3};"
        : "+f"(d[0]), "+f"(d[1]), "+f"(d[2]), "+f"(d[3])
        : "r"(a0), "r"(a1), "r"(a2), "r"(a3), "r"(b0), "r"(b1));
}
__device__ __forceinline__ void cpa16(void* smem_dst, const void* gsrc) {
    unsigned s = (unsigned)__cvta_generic_to_shared(smem_dst);
    asm volatile("cp.async.cg.shared.global [%0], [%1], 16;\n" :: "r"(s), "l"(gsrc));
}
__device__ __forceinline__ int perm8(int k) {
    return (k & ~7) + ((k & 3) * 2) + ((k >> 2) & 1);
}
__device__ __forceinline__ int posb(int P) {
    return ((P >> 3) * 16) + ((P & 3) * 4) + ((P >> 2) & 1);
}

// ---------------------------------------------------------------------------
// prep (unchanged)
// ---------------------------------------------------------------------------
__global__ void prep_kernel(
    const float* qg, const float* qb, const float* qm, const float* qv,
    const float* kg, const float* kb, const float* km, const float* kv,
    const float* vg, const float* vb, const float* vm, const float* vv,
    const float* og, const float* ob, const float* om, const float* ov)
{
    int i = blockIdx.x * blockDim.x + threadIdx.x;
    if (i < 1280) {
        const float *G, *B, *M, *V; float f; int r;
        if (i < 256)      { G = qg; B = qb; M = qm; V = qv; f = 0.044194173824159216f; r = i; }
        else if (i < 512) { G = kg; B = kb; M = km; V = kv; f = 1.0f / 1024.0f;        r = i - 256; }
        else if (i < 768) { G = vg; B = vb; M = vm; V = vv; f = 1.0f / 1024.0f;        r = i - 512; }
        else              { G = og; B = ob; M = om; V = ov; f = 1.0f;                  r = i - 768; }
        float s = G[r] * rsqrtf(V[r] + 1e-5f);
        g_pscale[i] = s * f;
        g_pbias[i]  = (B[r] - M[r] * s) * f;
    }
    int z = i - 1280;
    if (z >= 0 && z < HALF * NUM) g_kp[z] = 0.0f;
    z -= HALF * NUM;
    if (z >= 0 && z < NUM * HALF) g_vp[z] = 0.0f;
}

// ---------------------------------------------------------------------------
// QKV v5: q projection = tf32 (accuracy-critical); k/v projections = 1-pass
// bf16 m16n8k16 (pooling over 1024 pixels averages the bf16 noise to ~2e-4).
// Block 128(pix) x 128(oc), 2 blocks/SM, 2-stage cp.async. grid (6, 512).
// ---------------------------------------------------------------------------
#define QKV_SMEM ((2 * 32 * 136 + 2 * 128 * 36) * 4)
__global__ void __launch_bounds__(256, 2) qkv_kernel(
    const float* __restrict__ x, const float* __restrict__ qw,
    const float* __restrict__ kw, const float* __restrict__ vw)
{
    extern __shared__ float smq[];
    float* As = smq;                  // [2][32][136]  x tile [k][pix]
    float* Bs = smq + 2 * 32 * 136;   // [2][128][36]  W tile [oc][k]

    const int t = threadIdx.x, lane = t & 31, warp = t >> 5;
    const int g = lane >> 2, t4 = lane & 3;
    const int wm = (warp & 1) * 64, wn = (warp >> 1) * 32;
    const int gx = blockIdx.x;
    const int proj = gx >> 1, och = (gx & 1) * 128;
    const int pix0 = blockIdx.y * 128;
    const float* Wp = ((proj == 0) ? qw : (proj == 1) ? kw : vw) + (size_t)och * CIN;

    float acc[4][4][4] = {};

    const int a_row = t >> 5, a_c4 = (t & 31) * 4;
    const int b_oc  = t >> 3, b_c4 = (t & 7) * 4;

#define QKV_LOAD(s, k0)                                                        \
    {                                                                          \
        float* as = As + (s) * 32 * 136;                                       \
        float* bs = Bs + (s) * 128 * 36;                                       \
        _Pragma("unroll")                                                      \
        for (int i = 0; i < 4; i++)                                            \
            cpa16(as + (a_row + i * 8) * 136 + a_c4,                           \
                  x + (size_t)((k0) + a_row + i * 8) * HW + pix0 + a_c4);      \
        _Pragma("unroll")                                                      \
        for (int i = 0; i < 4; i++)                                            \
            cpa16(bs + (b_oc + i * 32) * 36 + b_c4,                            \
                  Wp + (size_t)(b_oc + i * 32) * CIN + (k0) + b_c4);           \
        asm volatile("cp.async.commit_group;\n");                              \
    }

    QKV_LOAD(0, 0);
    for (int kt = 0; kt < 16; kt++) {
        int s = kt & 1;
        if (kt < 15) {
            QKV_LOAD(s ^ 1, (kt + 1) * 32);
            asm volatile("cp.async.wait_group 1;\n");
        } else {
            asm volatile("cp.async.wait_group 0;\n");
        }
        __syncthreads();
        const float* as = As + s * 32 * 136;
        const float* bs = Bs + s * 128 * 36;
        if (proj == 0) {
            // tf32 path (q)
#pragma unroll
            for (int kk = 0; kk < 32; kk += 8) {
                unsigned a[4][4], b[4][2];
#pragma unroll
                for (int mi = 0; mi < 4; mi++) {
                    int mb = wm + mi * 16 + g;
                    a[mi][0] = __float_as_uint(as[(kk + t4) * 136 + mb]);
                    a[mi][1] = __float_as_uint(as[(kk + t4) * 136 + mb + 8]);
                    a[mi][2] = __float_as_uint(as[(kk + t4 + 4) * 136 + mb]);
                    a[mi][3] = __float_as_uint(as[(kk + t4 + 4) * 136 + mb + 8]);
                }
#pragma unroll
                for (int nj = 0; nj < 4; nj++) {
                    int nb = wn + nj * 8 + g;
                    b[nj][0] = __float_as_uint(bs[nb * 36 + kk + t4]);
                    b[nj][1] = __float_as_uint(bs[nb * 36 + kk + t4 + 4]);
                }
#pragma unroll
                for (int mi = 0; mi < 4; mi++)
#pragma unroll
                    for (int nj = 0; nj < 4; nj++)
                        mma8(acc[mi][nj], a[mi][0], a[mi][1], a[mi][2], a[mi][3],
                             b[nj][0], b[nj][1]);
            }
        } else {
            // bf16 1-pass path (k/v): half the tensor instructions
#pragma unroll
            for (int kk = 0; kk < 32; kk += 16) {
                unsigned a[4][4], b[4][2];
#pragma unroll
                for (int mi = 0; mi < 4; mi++) {
                    int mb = wm + mi * 16 + g;
                    a[mi][0] = pbf(as[(kk + 2 * t4) * 136 + mb],
                                   as[(kk + 2 * t4 + 1) * 136 + mb]);
                    a[mi][1] = pbf(as[(kk + 2 * t4) * 136 + mb + 8],
                                   as[(kk + 2 * t4 + 1) * 136 + mb + 8]);
                    a[mi][2] = pbf(as[(kk + 8 + 2 * t4) * 136 + mb],
                                   as[(kk + 9 + 2 * t4) * 136 + mb]);
                    a[mi][3] = pbf(as[(kk + 8 + 2 * t4) * 136 + mb + 8],
                                   as[(kk + 9 + 2 * t4) * 136 + mb + 8]);
                }
#pragma unroll
                for (int nj = 0; nj < 4; nj++) {
                    int nb = wn + nj * 8 + g;
                    float2 b0 = *(const float2*)&bs[nb * 36 + kk + 2 * t4];
                    float2 b1 = *(const float2*)&bs[nb * 36 + kk + 8 + 2 * t4];
                    b[nj][0] = pbf(b0.x, b0.y);
                    b[nj][1] = pbf(b1.x, b1.y);
                }
#pragma unroll
                for (int mi = 0; mi < 4; mi++)
#pragma unroll
                    for (int nj = 0; nj < 4; nj++)
                        mmabf(acc[mi][nj], a[mi][0], a[mi][1], a[mi][2], a[mi][3],
                              b[nj][0], b[nj][1]);
            }
        }
        __syncthreads();
    }
#undef QKV_LOAD

    if (proj == 0) {
#pragma unroll
        for (int mi = 0; mi < 4; mi++)
#pragma unroll
            for (int h2 = 0; h2 < 2; h2++) {
                int pix = pix0 + wm + mi * 16 + g + h2 * 8;
                int h = pix >> 8, w = pix & 255;
                int pn = (((h >> 5) << 3) + (w >> 5)) * NPP + ((h & 31) << 5) + (w & 31);
#pragma unroll
                for (int nj = 0; nj < 4; nj++) {
                    int col = och + wn + nj * 8 + t4 * 2;
                    float v0 = fmaxf(fmaf(acc[mi][nj][h2 * 2],     g_pscale[col],     g_pbias[col]),     0.0f);
                    float v1 = fmaxf(fmaf(acc[mi][nj][h2 * 2 + 1], g_pscale[col + 1], g_pbias[col + 1]), 0.0f);
                    *(float2*)&g_q[(size_t)pn * HALF + col] = make_float2(v0, v1);
                }
            }
    } else {
        float part[2][4][2] = {};
#pragma unroll
        for (int mi = 0; mi < 4; mi++) {
            int pl = mi >> 1;
#pragma unroll
            for (int nj = 0; nj < 4; nj++) {
                int sidx = proj * 256 + och + wn + nj * 8 + t4 * 2;
                float s0 = g_pscale[sidx],     b0 = g_pbias[sidx];
                float s1 = g_pscale[sidx + 1], b1 = g_pbias[sidx + 1];
#pragma unroll
                for (int h2 = 0; h2 < 2; h2++) {
                    part[pl][nj][0] += fmaxf(fmaf(acc[mi][nj][h2 * 2],     s0, b0), 0.0f);
                    part[pl][nj][1] += fmaxf(fmaf(acc[mi][nj][h2 * 2 + 1], s1, b1), 0.0f);
                }
            }
        }
#pragma unroll
        for (int m_ = 4; m_ <= 16; m_ <<= 1)
#pragma unroll
            for (int pl = 0; pl < 2; pl++)
#pragma unroll
                for (int nj = 0; nj < 4; nj++) {
                    part[pl][nj][0] += __shfl_xor_sync(0xffffffffu, part[pl][nj][0], m_);
                    part[pl][nj][1] += __shfl_xor_sync(0xffffffffu, part[pl][nj][1], m_);
                }
        if (g == 0) {
            int h0 = pix0 >> 8, w0 = pix0 & 255;
            int pbase = ((h0 >> 5) << 3) + (w0 >> 5);
#pragma unroll
            for (int pl = 0; pl < 2; pl++) {
                int p = pbase + (wm >> 5) + pl;
#pragma unroll
                for (int nj = 0; nj < 4; nj++) {
                    int oc2 = och + wn + nj * 8 + t4 * 2;
                    if (proj == 1) {
                        atomicAdd(&g_kp[oc2 * NUM + p],       part[pl][nj][0]);
                        atomicAdd(&g_kp[(oc2 + 1) * NUM + p], part[pl][nj][1]);
                    } else {
                        atomicAdd(&g_vp[p * HALF + oc2],     part[pl][nj][0]);
                        atomicAdd(&g_vp[p * HALF + oc2 + 1], part[pl][nj][1]);
                    }
                }
            }
        }
    }
}

// ---------------------------------------------------------------------------
// attnqk v3: cp.async double-buffered tiles (A as [pn][k] verbatim from g_q,
// B kp tiles verbatim), avt scatter staged through smem -> coalesced rows.
// ---------------------------------------------------------------------------
#define AQK_SMEM ((2 * 128 * 36 + 2 * 32 * 68) * 4)
__global__ void __launch_bounds__(256) attnqk_kernel()
{
    extern __shared__ float sma[];
    float* As = sma;                   // [2][128][36]  g_q tile [pn][k]
    float* Bs = sma + 2 * 128 * 36;    // [2][32][68]   kp tile [k][m]

    const int t = threadIdx.x, lane = t & 31, warp = t >> 5;
    const int wm = (warp & 3) * 32, wn = (warp >> 2) * 32;
    const int g = lane >> 2, t4 = lane & 3;
    const int pn0 = blockIdx.x * 128;
    const int p = pn0 >> 10, jt0 = (pn0 & 1023) >> 6;

    float acc[2][4][4] = {};

    const int a_row = t >> 1, a_half = t & 1;
    const int b_row = t >> 3, b_c = t & 7;

#define AQK_LOAD(s, k0)                                                        \
    {                                                                          \
        float* as = As + (s) * 128 * 36;                                       \
        float* bs = Bs + (s) * 32 * 68;                                        \
        _Pragma("unroll")                                                      \
        for (int i = 0; i < 4; i++)                                            \
            cpa16(as + a_row * 36 + (a_half * 4 + i) * 4,                      \
                  g_q + (size_t)(pn0 + a_row) * HALF + (k0) + (a_half * 4 + i) * 4); \
        _Pragma("unroll")                                                      \
        for (int i = 0; i < 2; i++)                                            \
            cpa16(bs + b_row * 68 + (b_c + i * 8) * 4,                         \
                  g_kp + (size_t)((k0) + b_row) * NUM + (b_c + i * 8) * 4);    \
        asm volatile("cp.async.commit_group;\n");                              \
    }

    AQK_LOAD(0, 0);
    for (int kt = 0; kt < 8; kt++) {
        int s = kt & 1;
        if (kt < 7) {
            AQK_LOAD(s ^ 1, (kt + 1) * 32);
            asm volatile("cp.async.wait_group 1;\n");
        } else {
            asm volatile("cp.async.wait_group 0;\n");
        }
        __syncthreads();
        const float* as = As + s * 128 * 36;
        const float* bs = Bs + s * 32 * 68;
#pragma unroll
        for (int kk = 0; kk < 32; kk += 8) {
            unsigned a[2][4], b[4][2];
#pragma unroll
            for (int mi = 0; mi < 2; mi++) {
                int mb = wm + mi * 16 + g;
                a[mi][0] = __float_as_uint(as[mb * 36 + kk + t4]);
                a[mi][1] = __float_as_uint(as[(mb + 8) * 36 + kk + t4]);
                a[mi][2] = __float_as_uint(as[mb * 36 + kk + t4 + 4]);
                a[mi][3] = __float_as_uint(as[(mb + 8) * 36 + kk + t4 + 4]);
            }
#pragma unroll
            for (int nj = 0; nj < 4; nj++) {
                int nb = wn + nj * 8 + g;
                b[nj][0] = __float_as_uint(bs[(kk + t4) * 68 + nb]);
                b[nj][1] = __float_as_uint(bs[(kk + t4 + 4) * 68 + nb]);
            }
#pragma unroll
            for (int mi = 0; mi < 2; mi++)
#pragma unroll
                for (int nj = 0; nj < 4; nj++)
                    mma8(acc[mi][nj], a[mi][0], a[mi][1], a[mi][2], a[mi][3],
                         b[nj][0], b[nj][1]);
        }
        __syncthreads();
    }
#undef AQK_LOAD

    // epilogue: abr written directly (row-blocked), avt staged in smem
    // stage[hh][col d][perm jl], pitch 68; reuses the As region (9216 >= 8704)
    float* stg = sma;
    const int hh = wm >> 6;
#pragma unroll
    for (int mi = 0; mi < 2; mi++)
#pragma unroll
        for (int h2 = 0; h2 < 2; h2++) {
            int rl = wm + mi * 16 + g + h2 * 8;    // row within block (0..127)
            int row = pn0 + rl;
            int jl = rl & 63;
            int pj = perm8(jl);
#pragma unroll
            for (int nj = 0; nj < 4; nj++) {
                int col = wn + nj * 8 + t4 * 2;
                float v0 = acc[mi][nj][h2 * 2], v1 = acc[mi][nj][h2 * 2 + 1];
                stg[(hh * 64 + col) * 68 + pj]     = t32(v0);
                stg[(hh * 64 + col + 1) * 68 + pj] = t32(v1);
                __nv_bfloat16 b0 = __float2bfloat16_rn(v0);
                __nv_bfloat16 b1 = __float2bfloat16_rn(v1);
                float r0 = v0 - __bfloat162float(b0);
                float r1 = v1 - __bfloat162float(b1);
                __nv_bfloat16 c0 = __float2bfloat16_rn(r0);
                __nv_bfloat16 c1 = __float2bfloat16_rn(r1);
                unsigned pb = (unsigned)__bfloat16_as_ushort(b0) |
                              ((unsigned)__bfloat16_as_ushort(b1) << 16);
                unsigned pr = (unsigned)__bfloat16_as_ushort(c0) |
                              ((unsigned)__bfloat16_as_ushort(c1) << 16);
                int P = col >> 1;
                int pbp = posb(P);
                g_abr[(size_t)row * 64 + pbp]     = pb;
                g_abr[(size_t)row * 64 + pbp + 2] = pr;
            }
        }
    __syncthreads();

    // coalesced avt writeout: 128 (hh,d) rows x 64 floats
    {
        int r = t >> 1, seg = t & 1;
        int h2h = r >> 6, d = r & 63;
        size_t vtb = ((size_t)p * 16 + jt0 + h2h) * 64;
        const float* srow = stg + (h2h * 64 + d) * 68 + seg * 32;
        float* drow = g_avt + (vtb + d) * 64 + seg * 32;
#pragma unroll
        for (int u = 0; u < 8; u++)
            *(float4*)(drow + u * 4) = *(const float4*)(srow + u * 4);
    }
}

// ---------------------------------------------------------------------------
// corr v6 (unchanged from R10)
// ---------------------------------------------------------------------------
#define CORR_SMEM ((2 * 64 * KBRP + 2 * 64 * VTP + 128 * KP) * 4)
__global__ void __launch_bounds__(256, 2) corr_kernel()
{
    extern __shared__ float sm[];
    unsigned* KbrA = (unsigned*)sm;
    float*    VtA  = (float*)(KbrA + 2 * 64 * KBRP);
    float*    Ps   = VtA + 2 * 64 * VTP;

    const int t = threadIdx.x, lane = t & 31, warp = t >> 5;
    const int g = lane >> 2, t4 = lane & 3;
    const int rm0 = warp * 16;
    const int n0 = blockIdx.x * 128;
    const int p  = blockIdx.y;
    const unsigned* abr = g_abr + (size_t)p * NPP * 64;
    const float*    avt = g_avt + (size_t)p * NPP * NUM;

    const int rl0 = n0 + rm0 + g, rl1 = rl0 + 8;
    const int pp0 = perm8(2 * t4), pp1 = perm8(2 * t4 + 1);

    unsigned qb[4][4], qr[4][4];
#pragma unroll
    for (int c = 0; c < 4; c++) {
        uint4 u0 = *(const uint4*)&abr[(size_t)rl0 * 64 + c * 16 + 4 * t4];
        uint4 u1 = *(const uint4*)&abr[(size_t)rl1 * 64 + c * 16 + 4 * t4];
        qb[c][0] = u0.x; qb[c][1] = u1.x; qb[c][2] = u0.y; qb[c][3] = u1.y;
        qr[c][0] = u0.z; qr[c][1] = u1.z; qr[c][2] = u0.w; qr[c][3] = u1.w;
    }

    const int lrow = t >> 4, lc4 = (t & 15) * 4;

#define CORR_LOAD(s, jt)                                                       \
    {                                                                          \
        unsigned* kbr = KbrA + (s) * 64 * KBRP;                                \
        float*    vt  = VtA  + (s) * 64 * VTP;                                 \
        _Pragma("unroll")                                                      \
        for (int i = 0; i < 4; i++) {                                          \
            int r = lrow + i * 16;                                             \
            cpa16(kbr + r * KBRP + lc4, abr + ((size_t)(jt) * 64 + r) * 64 + lc4); \
            cpa16(vt  + r * VTP  + lc4, avt + ((size_t)(jt) * 64 + r) * 64 + lc4); \
        }                                                                      \
        asm volatile("cp.async.commit_group;\n");                              \
    }

    float mi[2] = {-FLT_MAX, -FLT_MAX}, li[2] = {0.0f, 0.0f};
    float o[8][4] = {};

    CORR_LOAD(0, 0);
    for (int jt = 0; jt < 16; jt++) {
        int s = jt & 1;
        if (jt < 15) {
            CORR_LOAD(s ^ 1, jt + 1);
            asm volatile("cp.async.wait_group 1;\n");
        } else {
            asm volatile("cp.async.wait_group 0;\n");
        }
        __syncthreads();
        const unsigned* kbr = KbrA + s * 64 * KBRP;
        const float*    vt  = VtA  + s * 64 * VTP;

        float sa[8][4] = {};
#pragma unroll
        for (int c = 0; c < 4; c++) {
#pragma unroll
            for (int nj = 0; nj < 8; nj++) {
                uint4 b = *(const uint4*)&kbr[(nj * 8 + g) * KBRP + c * 16 + 4 * t4];
                mmabf(sa[nj], qb[c][0], qb[c][1], qb[c][2], qb[c][3], b.x, b.y);
                mmabf(sa[nj], qb[c][0], qb[c][1], qb[c][2], qb[c][3], b.z, b.w);
                mmabf(sa[nj], qr[c][0], qr[c][1], qr[c][2], qr[c][3], b.x, b.y);
            }
        }

#pragma unroll
        for (int h = 0; h < 2; h++) {
            float rmax = -FLT_MAX;
#pragma unroll
            for (int nj = 0; nj < 8; nj++)
                rmax = fmaxf(rmax, fmaxf(sa[nj][2 * h], sa[nj][2 * h + 1]));
            rmax = fmaxf(rmax, __shfl_xor_sync(0xffffffffu, rmax, 1));
            rmax = fmaxf(rmax, __shfl_xor_sync(0xffffffffu, rmax, 2));
            float nm = fmaxf(mi[h], rmax);
            float sc = __expf(mi[h] - nm);
            mi[h] = nm;
            float rs = 0.0f;
#pragma unroll
            for (int nj = 0; nj < 8; nj++) {
                float v0 = __expf(sa[nj][2 * h]     - nm);
                float v1 = __expf(sa[nj][2 * h + 1] - nm);
                sa[nj][2 * h] = v0; sa[nj][2 * h + 1] = v1;
                rs += v0 + v1;
            }
            rs += __shfl_xor_sync(0xffffffffu, rs, 1);
            rs += __shfl_xor_sync(0xffffffffu, rs, 2);
            li[h] = li[h] * sc + rs;
#pragma unroll
            for (int nj = 0; nj < 8; nj++) {
                o[nj][2 * h]     *= sc;
                o[nj][2 * h + 1] *= sc;
            }
        }

#pragma unroll
        for (int h = 0; h < 2; h++) {
            int rb = (rm0 + g + h * 8) * KP;
#pragma unroll
            for (int nj = 0; nj < 8; nj++) {
                Ps[rb + nj * 8 + pp0] = sa[nj][2 * h];
                Ps[rb + nj * 8 + pp1] = sa[nj][2 * h + 1];
            }
        }
        __syncwarp();

#pragma unroll
        for (int ks = 0; ks < 8; ks++) {
            int ko = ks * 8 + t4 * 2;
            float2 aA = *(const float2*)&Ps[(rm0 + g) * KP + ko];
            float2 aB = *(const float2*)&Ps[(rm0 + 8 + g) * KP + ko];
            unsigned a0 = __float_as_uint(aA.x), a1 = __float_as_uint(aB.x);
            unsigned a2 = __float_as_uint(aA.y), a3 = __float_as_uint(aB.y);
#pragma unroll
            for (int nj = 0; nj < 8; nj++) {
                float2 bv = *(const float2*)&vt[(nj * 8 + g) * VTP + ko];
                mma8(o[nj], a0, a1, a2, a3,
                     __float_as_uint(bv.x), __float_as_uint(bv.y));
            }
        }
        __syncthreads();
    }
#undef CORR_LOAD

#pragma unroll
    for (int h = 0; h < 2; h++) {
        int rl = (h == 0) ? rl0 : rl1;
        float inv = 1.0f / li[h];
        float tv[16];
#pragma unroll
        for (int nj = 0; nj < 8; nj++) {
            int pbp = posb(nj * 4 + t4);
            unsigned ub = abr[(size_t)rl * 64 + pbp];
            unsigned ur = abr[(size_t)rl * 64 + pbp + 2];
            float a0 = __uint_as_float(ub << 16) + __uint_as_float(ur << 16);
            float a1 = __uint_as_float(ub & 0xffff0000u) + __uint_as_float(ur & 0xffff0000u);
            tv[nj * 2]     = a0 + o[nj][2 * h]     * inv;
            tv[nj * 2 + 1] = a1 + o[nj][2 * h + 1] * inv;
        }
        float rmax = -FLT_MAX;
#pragma unroll
        for (int l = 0; l < 16; l++) rmax = fmaxf(rmax, tv[l]);
        rmax = fmaxf(rmax, __shfl_xor_sync(0xffffffffu, rmax, 1));
        rmax = fmaxf(rmax, __shfl_xor_sync(0xffffffffu, rmax, 2));
        float rs = 0.0f;
#pragma unroll
        for (int l = 0; l < 16; l++) { tv[l] = __expf(tv[l] - rmax); rs += tv[l]; }
        rs += __shfl_xor_sync(0xffffffffu, rs, 1);
        rs += __shfl_xor_sync(0xffffffffu, rs, 2);
        float is = 1.0f / rs;
        int rb = (rm0 + g + h * 8) * KP;
#pragma unroll
        for (int nj = 0; nj < 8; nj++) {
            Ps[rb + nj * 8 + pp0] = tv[nj * 2] * is;
            Ps[rb + nj * 8 + pp1] = tv[nj * 2 + 1] * is;
        }
    }

    float* Vs = VtA;
    const int lj = t >> 2, ld0 = (t & 3) * 16;
    const int lpj = perm8(lj);
    for (int ch = 0; ch < 4; ch++) {
        __syncthreads();
        {
            const float* src = g_vp + (size_t)lj * HALF + ch * 64 + ld0;
#pragma unroll
            for (int u = 0; u < 4; u++) {
                float4 v = *(const float4*)(src + u * 4);
                float vv[4] = {v.x, v.y, v.z, v.w};
#pragma unroll
                for (int c2 = 0; c2 < 4; c2++)
                    Vs[(ld0 + u * 4 + c2) * VTP + lpj] = vv[c2];
            }
        }
        __syncthreads();

        float acc[8][4] = {};
#pragma unroll
        for (int ks = 0; ks < 8; ks++) {
            int ko = ks * 8 + t4 * 2;
            float2 aA = *(const float2*)&Ps[(rm0 + g) * KP + ko];
            float2 aB = *(const float2*)&Ps[(rm0 + 8 + g) * KP + ko];
            unsigned a0 = __float_as_uint(aA.x), a1 = __float_as_uint(aB.x);
            unsigned a2 = __float_as_uint(aA.y), a3 = __float_as_uint(aB.y);
#pragma unroll
            for (int nj = 0; nj < 8; nj++) {
                float2 bv = *(const float2*)&Vs[(nj * 8 + g) * VTP + ko];
                mma8(acc[nj], a0, a1, a2, a3,
                     __float_as_uint(bv.x), __float_as_uint(bv.y));
            }
        }
#pragma unroll
        for (int h = 0; h < 2; h++) {
            size_t pn = (size_t)p * NPP + n0 + rm0 + g + h * 8;
#pragma unroll
            for (int nj = 0; nj < 8; nj++) {
                int col = ch * 64 + nj * 8 + 2 * t4;
                *(float2*)&g_mid[pn * HALF + col] =
                    make_float2(acc[nj][2 * h], acc[nj][2 * h + 1]);
            }
        }
    }
}

// ---------------------------------------------------------------------------
// o-proj v3 (unchanged from R10)
// ---------------------------------------------------------------------------
#define OPR_SMEM ((2 * 128 * 36 + 2 * 128 * 36) * 4)
__global__ void __launch_bounds__(256, 2) oproj_kernel(
    const float* __restrict__ x, const float* __restrict__ ow,
    float* __restrict__ out)
{
    extern __shared__ float smo[];
    float* As = smo;
    float* Bs = smo + 2 * 128 * 36;

    const int t = threadIdx.x, lane = t & 31, warp = t >> 5;
    const int g = lane >> 2, t4 = lane & 3;
    const int wm = (warp & 1) * 64, wn = (warp >> 1) * 32;
    const int ocr = blockIdx.x * 128;
    const int pn0 = blockIdx.y * 128;

    float acc[4][4][4] = {};

    const int a_row = t >> 3, a_c4 = (t & 7) * 4;

#define OPR_LOAD(s, k0)                                                        \
    {                                                                          \
        float* as = As + (s) * 128 * 36;                                       \
        float* bs = Bs + (s) * 128 * 36;                                       \
        _Pragma("unroll")                                                      \
        for (int i = 0; i < 4; i++)                                            \
            cpa16(as + (a_row + i * 32) * 36 + a_c4,                           \
                  g_mid + (size_t)(pn0 + a_row + i * 32) * HALF + (k0) + a_c4);\
        _Pragma("unroll")                                                      \
        for (int i = 0; i < 4; i++)                                            \
            cpa16(bs + (a_row + i * 32) * 36 + a_c4,                           \
                  ow + (size_t)(ocr + a_row + i * 32) * HALF + (k0) + a_c4);   \
        asm volatile("cp.async.commit_group;\n");                              \
    }

    OPR_LOAD(0, 0);
    for (int kt = 0; kt < 8; kt++) {
        int s = kt & 1;
        if (kt < 7) {
            OPR_LOAD(s ^ 1, (kt + 1) * 32);
            asm volatile("cp.async.wait_group 1;\n");
        } else {
            asm volatile("cp.async.wait_group 0;\n");
        }
        __syncthreads();
        const float* as = As + s * 128 * 36;
        const float* bs = Bs + s * 128 * 36;
#pragma unroll
        for (int kk = 0; kk < 32; kk += 8) {
            unsigned a[4][4], b[4][2];
#pragma unroll
            for (int mi = 0; mi < 4; mi++) {
                int mb = wm + mi * 16 + g;
                a[mi][0] = __float_as_uint(as[mb * 36 + kk + t4]);
                a[mi][1] = __float_as_uint(as[(mb + 8) * 36 + kk + t4]);
                a[mi][2] = __float_as_uint(as[mb * 36 + kk + t4 + 4]);
                a[mi][3] = __float_as_uint(as[(mb + 8) * 36 + kk + t4 + 4]);
            }
#pragma unroll
            for (int nj = 0; nj < 4; nj++) {
                int nb = wn + nj * 8 + g;
                b[nj][0] = __float_as_uint(bs[nb * 36 + kk + t4]);
                b[nj][1] = __float_as_uint(bs[nb * 36 + kk + t4 + 4]);
            }
#pragma unroll
            for (int mi = 0; mi < 4; mi++)
#pragma unroll
                for (int nj = 0; nj < 4; nj++)
                    mma8(acc[mi][nj], a[mi][0], a[mi][1], a[mi][2], a[mi][3],
                         b[nj][0], b[nj][1]);
        }
        __syncthreads();
    }
#undef OPR_LOAD

#pragma unroll
    for (int mi = 0; mi < 4; mi++)
#pragma unroll
        for (int h2 = 0; h2 < 2; h2++) {
            int pn = pn0 + wm + mi * 16 + g + h2 * 8;
            int p = pn >> 10, n = pn & 1023;
            int h = ((p >> 3) << 5) + (n >> 5);
            int w = ((p & 7) << 5) + (n & 31);
            int base = h * W_IMG + w;
#pragma unroll
            for (int nj = 0; nj < 4; nj++) {
                int oc = ocr + wn + nj * 8 + t4 * 2;
                float s0 = g_pscale[768 + oc],     b0 = g_pbias[768 + oc];
                float s1 = g_pscale[768 + oc + 1], b1 = g_pbias[768 + oc + 1];
                size_t i0 = (size_t)oc * HW + base;
                size_t i1 = i0 + HW;
                out[i0] = fmaxf(fmaf(acc[mi][nj][h2 * 2],     s0, b0), 0.0f) + x[i0];
                out[i1] = fmaxf(fmaf(acc[mi][nj][h2 * 2 + 1], s1, b1), 0.0f) + x[i1];
            }
        }
}

// ---------------------------------------------------------------------------
extern "C" void kernel_launch(void* const* d_in, const int* in_sizes, int n_in,
                              void* d_out, int out_size)
{
    (void)in_sizes; (void)n_in; (void)out_size;
    const float* x  = (const float*)d_in[0];
    const float* qw = (const float*)d_in[1];
    const float* kw = (const float*)d_in[6];
    const float* vw = (const float*)d_in[11];
    const float* ow = (const float*)d_in[16];

    cudaFuncSetAttribute(corr_kernel,
                         cudaFuncAttributeMaxDynamicSharedMemorySize, CORR_SMEM);
    cudaFuncSetAttribute(qkv_kernel,
                         cudaFuncAttributeMaxDynamicSharedMemorySize, QKV_SMEM);
    cudaFuncSetAttribute(attnqk_kernel,
                         cudaFuncAttributeMaxDynamicSharedMemorySize, AQK_SMEM);
    cudaFuncSetAttribute(oproj_kernel,
                         cudaFuncAttributeMaxDynamicSharedMemorySize, OPR_SMEM);

    prep_kernel<<<134, 256>>>(
        (const float*)d_in[2],  (const float*)d_in[3],  (const float*)d_in[4],  (const float*)d_in[5],
        (const float*)d_in[7],  (const float*)d_in[8],  (const float*)d_in[9],  (const float*)d_in[10],
        (const float*)d_in[12], (const float*)d_in[13], (const float*)d_in[14], (const float*)d_in[15],
        (const float*)d_in[17], (const float*)d_in[18], (const float*)d_in[19], (const float*)d_in[20]);

    qkv_kernel<<<dim3(6, 512), 256, QKV_SMEM>>>(x, qw, kw, vw);
    attnqk_kernel<<<512, 256, AQK_SMEM>>>();
    corr_kernel<<<dim3(8, 64), 256, CORR_SMEM>>>();
    oproj_kernel<<<dim3(4, 512), 256, OPR_SMEM>>>(x, ow, (float*)d_out);
}

// round 13
// speedup vs baseline: 1.0784x; 1.0784x over previous
#include <cuda_runtime.h>
#include <cuda_bf16.h>
#include <math.h>
#include <float.h>

#define HW    65536
#define CIN   512
#define HALF  256
#define NUM   64
#define NPP   1024
#define W_IMG 256
#define KP    72     // Ps pitch (floats)
#define KBRP  80     // interleaved big/res pitch (u32)
#define VTP   72     // Vt pitch (floats)

// scratch (device globals: allocation-free rule)
__device__ float    g_q[NUM * NPP * HALF];    // (pn, ch) q, scaled
__device__ float    g_kp[HALF * NUM];         // (ch, patch) pooled k
__device__ float    g_vp[NUM * HALF];         // (patch, ch) pooled v
__device__ unsigned g_abr[NUM * NPP * 64];    // attn bf16 big/res interleaved blocks
__device__ float    g_avt[NUM * NPP * NUM];   // attn tf32, [p][jt][d][perm(jl)]
__device__ float    g_mid[NUM * NPP * HALF];  // (pn, ch) attention output
__device__ float    g_pscale[1280];
__device__ float    g_pbias[1280];

// ---------------------------------------------------------------------------
__device__ __forceinline__ float t32(float x) {
    asm("cvt.rna.tf32.f32 %0, %0;" : "+f"(x));
    return x;
}
__device__ __forceinline__ void mma8(float* d,
    unsigned a0, unsigned a1, unsigned a2, unsigned a3,
    unsigned b0, unsigned b1)
{
    asm volatile(
        "mma.sync.aligned.m16n8k8.row.col.f32.tf32.tf32.f32 "
        "{%0,%1,%2,%3},{%4,%5,%6,%7},{%8,%9},{%0,%1,%2,%3};"
        : "+f"(d[0]), "+f"(d[1]), "+f"(d[2]), "+f"(d[3])
        : "r"(a0), "r"(a1), "r"(a2), "r"(a3), "r"(b0), "r"(b1));
}
__device__ __forceinline__ void mmabf(float* d,
    unsigned a0, unsigned a1, unsigned a2, unsigned a3,
    unsigned b0, unsigned b1)
{
    asm volatile(
        "mma.sync.aligned.m16n8k16.row.col.f32.bf16.bf16.f32 "
        "{%0,%1,%2,%3},{%4,%5,%6,%7},{%8,%9},{%0,%1,%2,%3};"
        : "+f"(d[0]), "+f"(d[1]), "+f"(d[2]), "+f"(d[3])
        : "r"(a0), "r"(a1), "r"(a2), "r"(a3), "r"(b0), "r"(b1));
}
__device__ __forceinline__ void cpa16(void* smem_dst, const void* gsrc) {
    unsigned s = (unsigned)__cvta_generic_to_shared(smem_dst);
    asm volatile("cp.async.cg.shared.global [%0], [%1], 16;\n" :: "r"(s), "l"(gsrc));
}
__device__ __forceinline__ int perm8(int k) {
    return (k & ~7) + ((k & 3) * 2) + ((k >> 2) & 1);
}
__device__ __forceinline__ int posb(int P) {
    return ((P >> 3) * 16) + ((P & 3) * 4) + ((P >> 2) & 1);
}

// ---------------------------------------------------------------------------
// prep (unchanged)
// ---------------------------------------------------------------------------
__global__ void prep_kernel(
    const float* qg, const float* qb, const float* qm, const float* qv,
    const float* kg, const float* kb, const float* km, const float* kv,
    const float* vg, const float* vb, const float* vm, const float* vv,
    const float* og, const float* ob, const float* om, const float* ov)
{
    int i = blockIdx.x * blockDim.x + threadIdx.x;
    if (i < 1280) {
        const float *G, *B, *M, *V; float f; int r;
        if (i < 256)      { G = qg; B = qb; M = qm; V = qv; f = 0.044194173824159216f; r = i; }
        else if (i < 512) { G = kg; B = kb; M = km; V = kv; f = 1.0f / 1024.0f;        r = i - 256; }
        else if (i < 768) { G = vg; B = vb; M = vm; V = vv; f = 1.0f / 1024.0f;        r = i - 512; }
        else              { G = og; B = ob; M = om; V = ov; f = 1.0f;                  r = i - 768; }
        float s = G[r] * rsqrtf(V[r] + 1e-5f);
        g_pscale[i] = s * f;
        g_pbias[i]  = (B[r] - M[r] * s) * f;
    }
    int z = i - 1280;
    if (z >= 0 && z < HALF * NUM) g_kp[z] = 0.0f;
    z -= HALF * NUM;
    if (z >= 0 && z < NUM * HALF) g_vp[z] = 0.0f;
}

// ---------------------------------------------------------------------------
// QKV v3 (R10 version: all-tf32, raw weight pointers, 36-pitch tiles)
// ---------------------------------------------------------------------------
#define QKV_SMEM ((2 * 32 * 136 + 2 * 128 * 36) * 4)
__global__ void __launch_bounds__(256, 2) qkv_kernel(
    const float* __restrict__ x, const float* __restrict__ qw,
    const float* __restrict__ kw, const float* __restrict__ vw)
{
    extern __shared__ float smq[];
    float* As = smq;
    float* Bs = smq + 2 * 32 * 136;

    const int t = threadIdx.x, lane = t & 31, warp = t >> 5;
    const int g = lane >> 2, t4 = lane & 3;
    const int wm = (warp & 1) * 64, wn = (warp >> 1) * 32;
    const int gx = blockIdx.x;
    const int proj = gx >> 1, och = (gx & 1) * 128;
    const int pix0 = blockIdx.y * 128;
    const float* Wp = ((proj == 0) ? qw : (proj == 1) ? kw : vw) + (size_t)och * CIN;

    float acc[4][4][4] = {};

    const int a_row = t >> 5, a_c4 = (t & 31) * 4;
    const int b_oc  = t >> 3, b_c4 = (t & 7) * 4;

#define QKV_LOAD(s, k0)                                                        \
    {                                                                          \
        float* as = As + (s) * 32 * 136;                                       \
        float* bs = Bs + (s) * 128 * 36;                                       \
        _Pragma("unroll")                                                      \
        for (int i = 0; i < 4; i++)                                            \
            cpa16(as + (a_row + i * 8) * 136 + a_c4,                           \
                  x + (size_t)((k0) + a_row + i * 8) * HW + pix0 + a_c4);      \
        _Pragma("unroll")                                                      \
        for (int i = 0; i < 4; i++)                                            \
            cpa16(bs + (b_oc + i * 32) * 36 + b_c4,                            \
                  Wp + (size_t)(b_oc + i * 32) * CIN + (k0) + b_c4);           \
        asm volatile("cp.async.commit_group;\n");                              \
    }

    QKV_LOAD(0, 0);
    for (int kt = 0; kt < 16; kt++) {
        int s = kt & 1;
        if (kt < 15) {
            QKV_LOAD(s ^ 1, (kt + 1) * 32);
            asm volatile("cp.async.wait_group 1;\n");
        } else {
            asm volatile("cp.async.wait_group 0;\n");
        }
        __syncthreads();
        const float* as = As + s * 32 * 136;
        const float* bs = Bs + s * 128 * 36;
#pragma unroll
        for (int kk = 0; kk < 32; kk += 8) {
            unsigned a[4][4], b[4][2];
#pragma unroll
            for (int mi = 0; mi < 4; mi++) {
                int mb = wm + mi * 16 + g;
                a[mi][0] = __float_as_uint(as[(kk + t4) * 136 + mb]);
                a[mi][1] = __float_as_uint(as[(kk + t4) * 136 + mb + 8]);
                a[mi][2] = __float_as_uint(as[(kk + t4 + 4) * 136 + mb]);
                a[mi][3] = __float_as_uint(as[(kk + t4 + 4) * 136 + mb + 8]);
            }
#pragma unroll
            for (int nj = 0; nj < 4; nj++) {
                int nb = wn + nj * 8 + g;
                b[nj][0] = __float_as_uint(bs[nb * 36 + kk + t4]);
                b[nj][1] = __float_as_uint(bs[nb * 36 + kk + t4 + 4]);
            }
#pragma unroll
            for (int mi = 0; mi < 4; mi++)
#pragma unroll
                for (int nj = 0; nj < 4; nj++)
                    mma8(acc[mi][nj], a[mi][0], a[mi][1], a[mi][2], a[mi][3],
                         b[nj][0], b[nj][1]);
        }
        __syncthreads();
    }
#undef QKV_LOAD

    if (proj == 0) {
#pragma unroll
        for (int mi = 0; mi < 4; mi++)
#pragma unroll
            for (int h2 = 0; h2 < 2; h2++) {
                int pix = pix0 + wm + mi * 16 + g + h2 * 8;
                int h = pix >> 8, w = pix & 255;
                int pn = (((h >> 5) << 3) + (w >> 5)) * NPP + ((h & 31) << 5) + (w & 31);
#pragma unroll
                for (int nj = 0; nj < 4; nj++) {
                    int col = och + wn + nj * 8 + t4 * 2;
                    float v0 = fmaxf(fmaf(acc[mi][nj][h2 * 2],     g_pscale[col],     g_pbias[col]),     0.0f);
                    float v1 = fmaxf(fmaf(acc[mi][nj][h2 * 2 + 1], g_pscale[col + 1], g_pbias[col + 1]), 0.0f);
                    *(float2*)&g_q[(size_t)pn * HALF + col] = make_float2(v0, v1);
                }
            }
    } else {
        float part[2][4][2] = {};
#pragma unroll
        for (int mi = 0; mi < 4; mi++) {
            int pl = mi >> 1;
#pragma unroll
            for (int nj = 0; nj < 4; nj++) {
                int sidx = proj * 256 + och + wn + nj * 8 + t4 * 2;
                float s0 = g_pscale[sidx],     b0 = g_pbias[sidx];
                float s1 = g_pscale[sidx + 1], b1 = g_pbias[sidx + 1];
#pragma unroll
                for (int h2 = 0; h2 < 2; h2++) {
                    part[pl][nj][0] += fmaxf(fmaf(acc[mi][nj][h2 * 2],     s0, b0), 0.0f);
                    part[pl][nj][1] += fmaxf(fmaf(acc[mi][nj][h2 * 2 + 1], s1, b1), 0.0f);
                }
            }
        }
#pragma unroll
        for (int m_ = 4; m_ <= 16; m_ <<= 1)
#pragma unroll
            for (int pl = 0; pl < 2; pl++)
#pragma unroll
                for (int nj = 0; nj < 4; nj++) {
                    part[pl][nj][0] += __shfl_xor_sync(0xffffffffu, part[pl][nj][0], m_);
                    part[pl][nj][1] += __shfl_xor_sync(0xffffffffu, part[pl][nj][1], m_);
                }
        if (g == 0) {
            int h0 = pix0 >> 8, w0 = pix0 & 255;
            int pbase = ((h0 >> 5) << 3) + (w0 >> 5);
#pragma unroll
            for (int pl = 0; pl < 2; pl++) {
                int p = pbase + (wm >> 5) + pl;
#pragma unroll
                for (int nj = 0; nj < 4; nj++) {
                    int oc2 = och + wn + nj * 8 + t4 * 2;
                    if (proj == 1) {
                        atomicAdd(&g_kp[oc2 * NUM + p],       part[pl][nj][0]);
                        atomicAdd(&g_kp[(oc2 + 1) * NUM + p], part[pl][nj][1]);
                    } else {
                        atomicAdd(&g_vp[p * HALF + oc2],     part[pl][nj][0]);
                        atomicAdd(&g_vp[p * HALF + oc2 + 1], part[pl][nj][1]);
                    }
                }
            }
        }
    }
}

// ---------------------------------------------------------------------------
// attnqk v3 (the ONE change vs R10): cp.async double-buffered tiles, avt
// scatter staged through smem -> coalesced 128B rows.
// ---------------------------------------------------------------------------
#define AQK_SMEM ((2 * 128 * 36 + 2 * 32 * 68) * 4)
__global__ void __launch_bounds__(256) attnqk_kernel()
{
    extern __shared__ float sma[];
    float* As = sma;                   // [2][128][36]  g_q tile [pn][k]
    float* Bs = sma + 2 * 128 * 36;    // [2][32][68]   kp tile [k][m]

    const int t = threadIdx.x, lane = t & 31, warp = t >> 5;
    const int wm = (warp & 3) * 32, wn = (warp >> 2) * 32;
    const int g = lane >> 2, t4 = lane & 3;
    const int pn0 = blockIdx.x * 128;
    const int p = pn0 >> 10, jt0 = (pn0 & 1023) >> 6;

    float acc[2][4][4] = {};

    const int a_row = t >> 1, a_half = t & 1;
    const int b_row = t >> 3, b_c = t & 7;

#define AQK_LOAD(s, k0)                                                        \
    {                                                                          \
        float* as = As + (s) * 128 * 36;                                       \
        float* bs = Bs + (s) * 32 * 68;                                        \
        _Pragma("unroll")                                                      \
        for (int i = 0; i < 4; i++)                                            \
            cpa16(as + a_row * 36 + (a_half * 4 + i) * 4,                      \
                  g_q + (size_t)(pn0 + a_row) * HALF + (k0) + (a_half * 4 + i) * 4); \
        _Pragma("unroll")                                                      \
        for (int i = 0; i < 2; i++)                                            \
            cpa16(bs + b_row * 68 + (b_c + i * 8) * 4,                         \
                  g_kp + (size_t)((k0) + b_row) * NUM + (b_c + i * 8) * 4);    \
        asm volatile("cp.async.commit_group;\n");                              \
    }

    AQK_LOAD(0, 0);
    for (int kt = 0; kt < 8; kt++) {
        int s = kt & 1;
        if (kt < 7) {
            AQK_LOAD(s ^ 1, (kt + 1) * 32);
            asm volatile("cp.async.wait_group 1;\n");
        } else {
            asm volatile("cp.async.wait_group 0;\n");
        }
        __syncthreads();
        const float* as = As + s * 128 * 36;
        const float* bs = Bs + s * 32 * 68;
#pragma unroll
        for (int kk = 0; kk < 32; kk += 8) {
            unsigned a[2][4], b[4][2];
#pragma unroll
            for (int mi = 0; mi < 2; mi++) {
                int mb = wm + mi * 16 + g;
                a[mi][0] = __float_as_uint(as[mb * 36 + kk + t4]);
                a[mi][1] = __float_as_uint(as[(mb + 8) * 36 + kk + t4]);
                a[mi][2] = __float_as_uint(as[mb * 36 + kk + t4 + 4]);
                a[mi][3] = __float_as_uint(as[(mb + 8) * 36 + kk + t4 + 4]);
            }
#pragma unroll
            for (int nj = 0; nj < 4; nj++) {
                int nb = wn + nj * 8 + g;
                b[nj][0] = __float_as_uint(bs[(kk + t4) * 68 + nb]);
                b[nj][1] = __float_as_uint(bs[(kk + t4 + 4) * 68 + nb]);
            }
#pragma unroll
            for (int mi = 0; mi < 2; mi++)
#pragma unroll
                for (int nj = 0; nj < 4; nj++)
                    mma8(acc[mi][nj], a[mi][0], a[mi][1], a[mi][2], a[mi][3],
                         b[nj][0], b[nj][1]);
        }
        __syncthreads();
    }
#undef AQK_LOAD

    // epilogue: abr written directly (row-blocked), avt staged in smem
    float* stg = sma;
    const int hh = wm >> 6;
#pragma unroll
    for (int mi = 0; mi < 2; mi++)
#pragma unroll
        for (int h2 = 0; h2 < 2; h2++) {
            int rl = wm + mi * 16 + g + h2 * 8;
            int row = pn0 + rl;
            int jl = rl & 63;
            int pj = perm8(jl);
#pragma unroll
            for (int nj = 0; nj < 4; nj++) {
                int col = wn + nj * 8 + t4 * 2;
                float v0 = acc[mi][nj][h2 * 2], v1 = acc[mi][nj][h2 * 2 + 1];
                stg[(hh * 64 + col) * 68 + pj]     = t32(v0);
                stg[(hh * 64 + col + 1) * 68 + pj] = t32(v1);
                __nv_bfloat16 b0 = __float2bfloat16_rn(v0);
                __nv_bfloat16 b1 = __float2bfloat16_rn(v1);
                float r0 = v0 - __bfloat162float(b0);
                float r1 = v1 - __bfloat162float(b1);
                __nv_bfloat16 c0 = __float2bfloat16_rn(r0);
                __nv_bfloat16 c1 = __float2bfloat16_rn(r1);
                unsigned pb = (unsigned)__bfloat16_as_ushort(b0) |
                              ((unsigned)__bfloat16_as_ushort(b1) << 16);
                unsigned pr = (unsigned)__bfloat16_as_ushort(c0) |
                              ((unsigned)__bfloat16_as_ushort(c1) << 16);
                int P = col >> 1;
                int pbp = posb(P);
                g_abr[(size_t)row * 64 + pbp]     = pb;
                g_abr[(size_t)row * 64 + pbp + 2] = pr;
            }
        }
    __syncthreads();

    // coalesced avt writeout: 128 (hh,d) rows x 64 floats
    {
        int r = t >> 1, seg = t & 1;
        int h2h = r >> 6, d = r & 63;
        size_t vtb = ((size_t)p * 16 + jt0 + h2h) * 64;
        const float* srow = stg + (h2h * 64 + d) * 68 + seg * 32;
        float* drow = g_avt + (vtb + d) * 64 + seg * 32;
#pragma unroll
        for (int u = 0; u < 8; u++)
            *(float4*)(drow + u * 4) = *(const float4*)(srow + u * 4);
    }
}

// ---------------------------------------------------------------------------
// corr v6 (unchanged from R10)
// ---------------------------------------------------------------------------
#define CORR_SMEM ((2 * 64 * KBRP + 2 * 64 * VTP + 128 * KP) * 4)
__global__ void __launch_bounds__(256, 2) corr_kernel()
{
    extern __shared__ float sm[];
    unsigned* KbrA = (unsigned*)sm;
    float*    VtA  = (float*)(KbrA + 2 * 64 * KBRP);
    float*    Ps   = VtA + 2 * 64 * VTP;

    const int t = threadIdx.x, lane = t & 31, warp = t >> 5;
    const int g = lane >> 2, t4 = lane & 3;
    const int rm0 = warp * 16;
    const int n0 = blockIdx.x * 128;
    const int p  = blockIdx.y;
    const unsigned* abr = g_abr + (size_t)p * NPP * 64;
    const float*    avt = g_avt + (size_t)p * NPP * NUM;

    const int rl0 = n0 + rm0 + g, rl1 = rl0 + 8;
    const int pp0 = perm8(2 * t4), pp1 = perm8(2 * t4 + 1);

    unsigned qb[4][4], qr[4][4];
#pragma unroll
    for (int c = 0; c < 4; c++) {
        uint4 u0 = *(const uint4*)&abr[(size_t)rl0 * 64 + c * 16 + 4 * t4];
        uint4 u1 = *(const uint4*)&abr[(size_t)rl1 * 64 + c * 16 + 4 * t4];
        qb[c][0] = u0.x; qb[c][1] = u1.x; qb[c][2] = u0.y; qb[c][3] = u1.y;
        qr[c][0] = u0.z; qr[c][1] = u1.z; qr[c][2] = u0.w; qr[c][3] = u1.w;
    }

    const int lrow = t >> 4, lc4 = (t & 15) * 4;

#define CORR_LOAD(s, jt)                                                       \
    {                                                                          \
        unsigned* kbr = KbrA + (s) * 64 * KBRP;                                \
        float*    vt  = VtA  + (s) * 64 * VTP;                                 \
        _Pragma("unroll")                                                      \
        for (int i = 0; i < 4; i++) {                                          \
            int r = lrow + i * 16;                                             \
            cpa16(kbr + r * KBRP + lc4, abr + ((size_t)(jt) * 64 + r) * 64 + lc4); \
            cpa16(vt  + r * VTP  + lc4, avt + ((size_t)(jt) * 64 + r) * 64 + lc4); \
        }                                                                      \
        asm volatile("cp.async.commit_group;\n");                              \
    }

    float mi[2] = {-FLT_MAX, -FLT_MAX}, li[2] = {0.0f, 0.0f};
    float o[8][4] = {};

    CORR_LOAD(0, 0);
    for (int jt = 0; jt < 16; jt++) {
        int s = jt & 1;
        if (jt < 15) {
            CORR_LOAD(s ^ 1, jt + 1);
            asm volatile("cp.async.wait_group 1;\n");
        } else {
            asm volatile("cp.async.wait_group 0;\n");
        }
        __syncthreads();
        const unsigned* kbr = KbrA + s * 64 * KBRP;
        const float*    vt  = VtA  + s * 64 * VTP;

        float sa[8][4] = {};
#pragma unroll
        for (int c = 0; c < 4; c++) {
#pragma unroll
            for (int nj = 0; nj < 8; nj++) {
                uint4 b = *(const uint4*)&kbr[(nj * 8 + g) * KBRP + c * 16 + 4 * t4];
                mmabf(sa[nj], qb[c][0], qb[c][1], qb[c][2], qb[c][3], b.x, b.y);
                mmabf(sa[nj], qb[c][0], qb[c][1], qb[c][2], qb[c][3], b.z, b.w);
                mmabf(sa[nj], qr[c][0], qr[c][1], qr[c][2], qr[c][3], b.x, b.y);
            }
        }

#pragma unroll
        for (int h = 0; h < 2; h++) {
            float rmax = -FLT_MAX;
#pragma unroll
            for (int nj = 0; nj < 8; nj++)
                rmax = fmaxf(rmax, fmaxf(sa[nj][2 * h], sa[nj][2 * h + 1]));
            rmax = fmaxf(rmax, __shfl_xor_sync(0xffffffffu, rmax, 1));
            rmax = fmaxf(rmax, __shfl_xor_sync(0xffffffffu, rmax, 2));
            float nm = fmaxf(mi[h], rmax);
            float sc = __expf(mi[h] - nm);
            mi[h] = nm;
            float rs = 0.0f;
#pragma unroll
            for (int nj = 0; nj < 8; nj++) {
                float v0 = __expf(sa[nj][2 * h]     - nm);
                float v1 = __expf(sa[nj][2 * h + 1] - nm);
                sa[nj][2 * h] = v0; sa[nj][2 * h + 1] = v1;
                rs += v0 + v1;
            }
            rs += __shfl_xor_sync(0xffffffffu, rs, 1);
            rs += __shfl_xor_sync(0xffffffffu, rs, 2);
            li[h] = li[h] * sc + rs;
#pragma unroll
            for (int nj = 0; nj < 8; nj++) {
                o[nj][2 * h]     *= sc;
                o[nj][2 * h + 1] *= sc;
            }
        }

#pragma unroll
        for (int h = 0; h < 2; h++) {
            int rb = (rm0 + g + h * 8) * KP;
#pragma unroll
            for (int nj = 0; nj < 8; nj++) {
                Ps[rb + nj * 8 + pp0] = sa[nj][2 * h];
                Ps[rb + nj * 8 + pp1] = sa[nj][2 * h + 1];
            }
        }
        __syncwarp();

#pragma unroll
        for (int ks = 0; ks < 8; ks++) {
            int ko = ks * 8 + t4 * 2;
            float2 aA = *(const float2*)&Ps[(rm0 + g) * KP + ko];
            float2 aB = *(const float2*)&Ps[(rm0 + 8 + g) * KP + ko];
            unsigned a0 = __float_as_uint(aA.x), a1 = __float_as_uint(aB.x);
            unsigned a2 = __float_as_uint(aA.y), a3 = __float_as_uint(aB.y);
#pragma unroll
            for (int nj = 0; nj < 8; nj++) {
                float2 bv = *(const float2*)&vt[(nj * 8 + g) * VTP + ko];
                mma8(o[nj], a0, a1, a2, a3,
                     __float_as_uint(bv.x), __float_as_uint(bv.y));
            }
        }
        __syncthreads();
    }
#undef CORR_LOAD

#pragma unroll
    for (int h = 0; h < 2; h++) {
        int rl = (h == 0) ? rl0 : rl1;
        float inv = 1.0f / li[h];
        float tv[16];
#pragma unroll
        for (int nj = 0; nj < 8; nj++) {
            int pbp = posb(nj * 4 + t4);
            unsigned ub = abr[(size_t)rl * 64 + pbp];
            unsigned ur = abr[(size_t)rl * 64 + pbp + 2];
            float a0 = __uint_as_float(ub << 16) + __uint_as_float(ur << 16);
            float a1 = __uint_as_float(ub & 0xffff0000u) + __uint_as_float(ur & 0xffff0000u);
            tv[nj * 2]     = a0 + o[nj][2 * h]     * inv;
            tv[nj * 2 + 1] = a1 + o[nj][2 * h + 1] * inv;
        }
        float rmax = -FLT_MAX;
#pragma unroll
        for (int l = 0; l < 16; l++) rmax = fmaxf(rmax, tv[l]);
        rmax = fmaxf(rmax, __shfl_xor_sync(0xffffffffu, rmax, 1));
        rmax = fmaxf(rmax, __shfl_xor_sync(0xffffffffu, rmax, 2));
        float rs = 0.0f;
#pragma unroll
        for (int l = 0; l < 16; l++) { tv[l] = __expf(tv[l] - rmax); rs += tv[l]; }
        rs += __shfl_xor_sync(0xffffffffu, rs, 1);
        rs += __shfl_xor_sync(0xffffffffu, rs, 2);
        float is = 1.0f / rs;
        int rb = (rm0 + g + h * 8) * KP;
#pragma unroll
        for (int nj = 0; nj < 8; nj++) {
            Ps[rb + nj * 8 + pp0] = tv[nj * 2] * is;
            Ps[rb + nj * 8 + pp1] = tv[nj * 2 + 1] * is;
        }
    }

    float* Vs = VtA;
    const int lj = t >> 2, ld0 = (t & 3) * 16;
    const int lpj = perm8(lj);
    for (int ch = 0; ch < 4; ch++) {
        __syncthreads();
        {
            const float* src = g_vp + (size_t)lj * HALF + ch * 64 + ld0;
#pragma unroll
            for (int u = 0; u < 4; u++) {
                float4 v = *(const float4*)(src + u * 4);
                float vv[4] = {v.x, v.y, v.z, v.w};
#pragma unroll
                for (int c2 = 0; c2 < 4; c2++)
                    Vs[(ld0 + u * 4 + c2) * VTP + lpj] = vv[c2];
            }
        }
        __syncthreads();

        float acc[8][4] = {};
#pragma unroll
        for (int ks = 0; ks < 8; ks++) {
            int ko = ks * 8 + t4 * 2;
            float2 aA = *(const float2*)&Ps[(rm0 + g) * KP + ko];
            float2 aB = *(const float2*)&Ps[(rm0 + 8 + g) * KP + ko];
            unsigned a0 = __float_as_uint(aA.x), a1 = __float_as_uint(aB.x);
            unsigned a2 = __float_as_uint(aA.y), a3 = __float_as_uint(aB.y);
#pragma unroll
            for (int nj = 0; nj < 8; nj++) {
                float2 bv = *(const float2*)&Vs[(nj * 8 + g) * VTP + ko];
                mma8(acc[nj], a0, a1, a2, a3,
                     __float_as_uint(bv.x), __float_as_uint(bv.y));
            }
        }
#pragma unroll
        for (int h = 0; h < 2; h++) {
            size_t pn = (size_t)p * NPP + n0 + rm0 + g + h * 8;
#pragma unroll
            for (int nj = 0; nj < 8; nj++) {
                int col = ch * 64 + nj * 8 + 2 * t4;
                *(float2*)&g_mid[pn * HALF + col] =
                    make_float2(acc[nj][2 * h], acc[nj][2 * h + 1]);
            }
        }
    }
}

// ---------------------------------------------------------------------------
// o-proj v3 (unchanged from R10)
// ---------------------------------------------------------------------------
#define OPR_SMEM ((2 * 128 * 36 + 2 * 128 * 36) * 4)
__global__ void __launch_bounds__(256, 2) oproj_kernel(
    const float* __restrict__ x, const float* __restrict__ ow,
    float* __restrict__ out)
{
    extern __shared__ float smo[];
    float* As = smo;
    float* Bs = smo + 2 * 128 * 36;

    const int t = threadIdx.x, lane = t & 31, warp = t >> 5;
    const int g = lane >> 2, t4 = lane & 3;
    const int wm = (warp & 1) * 64, wn = (warp >> 1) * 32;
    const int ocr = blockIdx.x * 128;
    const int pn0 = blockIdx.y * 128;

    float acc[4][4][4] = {};

    const int a_row = t >> 3, a_c4 = (t & 7) * 4;

#define OPR_LOAD(s, k0)                                                        \
    {                                                                          \
        float* as = As + (s) * 128 * 36;                                       \
        float* bs = Bs + (s) * 128 * 36;                                       \
        _Pragma("unroll")                                                      \
        for (int i = 0; i < 4; i++)                                            \
            cpa16(as + (a_row + i * 32) * 36 + a_c4,                           \
                  g_mid + (size_t)(pn0 + a_row + i * 32) * HALF + (k0) + a_c4);\
        _Pragma("unroll")                                                      \
        for (int i = 0; i < 4; i++)                                            \
            cpa16(bs + (a_row + i * 32) * 36 + a_c4,                           \
                  ow + (size_t)(ocr + a_row + i * 32) * HALF + (k0) + a_c4);   \
        asm volatile("cp.async.commit_group;\n");                              \
    }

    OPR_LOAD(0, 0);
    for (int kt = 0; kt < 8; kt++) {
        int s = kt & 1;
        if (kt < 7) {
            OPR_LOAD(s ^ 1, (kt + 1) * 32);
            asm volatile("cp.async.wait_group 1;\n");
        } else {
            asm volatile("cp.async.wait_group 0;\n");
        }
        __syncthreads();
        const float* as = As + s * 128 * 36;
        const float* bs = Bs + s * 128 * 36;
#pragma unroll
        for (int kk = 0; kk < 32; kk += 8) {
            unsigned a[4][4], b[4][2];
#pragma unroll
            for (int mi = 0; mi < 4; mi++) {
                int mb = wm + mi * 16 + g;
                a[mi][0] = __float_as_uint(as[mb * 36 + kk + t4]);
                a[mi][1] = __float_as_uint(as[(mb + 8) * 36 + kk + t4]);
                a[mi][2] = __float_as_uint(as[mb * 36 + kk + t4 + 4]);
                a[mi][3] = __float_as_uint(as[(mb + 8) * 36 + kk + t4 + 4]);
            }
#pragma unroll
            for (int nj = 0; nj < 4; nj++) {
                int nb = wn + nj * 8 + g;
                b[nj][0] = __float_as_uint(bs[nb * 36 + kk + t4]);
                b[nj][1] = __float_as_uint(bs[nb * 36 + kk + t4 + 4]);
            }
#pragma unroll
            for (int mi = 0; mi < 4; mi++)
#pragma unroll
                for (int nj = 0; nj < 4; nj++)
                    mma8(acc[mi][nj], a[mi][0], a[mi][1], a[mi][2], a[mi][3],
                         b[nj][0], b[nj][1]);
        }
        __syncthreads();
    }
#undef OPR_LOAD

#pragma unroll
    for (int mi = 0; mi < 4; mi++)
#pragma unroll
        for (int h2 = 0; h2 < 2; h2++) {
            int pn = pn0 + wm + mi * 16 + g + h2 * 8;
            int p = pn >> 10, n = pn & 1023;
            int h = ((p >> 3) << 5) + (n >> 5);
            int w = ((p & 7) << 5) + (n & 31);
            int base = h * W_IMG + w;
#pragma unroll
            for (int nj = 0; nj < 4; nj++) {
                int oc = ocr + wn + nj * 8 + t4 * 2;
                float s0 = g_pscale[768 + oc],     b0 = g_pbias[768 + oc];
                float s1 = g_pscale[768 + oc + 1], b1 = g_pbias[768 + oc + 1];
                size_t i0 = (size_t)oc * HW + base;
                size_t i1 = i0 + HW;
                out[i0] = fmaxf(fmaf(acc[mi][nj][h2 * 2],     s0, b0), 0.0f) + x[i0];
                out[i1] = fmaxf(fmaf(acc[mi][nj][h2 * 2 + 1], s1, b1), 0.0f) + x[i1];
            }
        }
}

// ---------------------------------------------------------------------------
extern "C" void kernel_launch(void* const* d_in, const int* in_sizes, int n_in,
                              void* d_out, int out_size)
{
    (void)in_sizes; (void)n_in; (void)out_size;
    const float* x  = (const float*)d_in[0];
    const float* qw = (const float*)d_in[1];
    const float* kw = (const float*)d_in[6];
    const float* vw = (const float*)d_in[11];
    const float* ow = (const float*)d_in[16];

    cudaFuncSetAttribute(corr_kernel,
                         cudaFuncAttributeMaxDynamicSharedMemorySize, CORR_SMEM);
    cudaFuncSetAttribute(qkv_kernel,
                         cudaFuncAttributeMaxDynamicSharedMemorySize, QKV_SMEM);
    cudaFuncSetAttribute(attnqk_kernel,
                         cudaFuncAttributeMaxDynamicSharedMemorySize, AQK_SMEM);
    cudaFuncSetAttribute(oproj_kernel,
                         cudaFuncAttributeMaxDynamicSharedMemorySize, OPR_SMEM);

    prep_kernel<<<134, 256>>>(
        (const float*)d_in[2],  (const float*)d_in[3],  (const float*)d_in[4],  (const float*)d_in[5],
        (const float*)d_in[7],  (const float*)d_in[8],  (const float*)d_in[9],  (const float*)d_in[10],
        (const float*)d_in[12], (const float*)d_in[13], (const float*)d_in[14], (const float*)d_in[15],
        (const float*)d_in[17], (const float*)d_in[18], (const float*)d_in[19], (const float*)d_in[20]);

    qkv_kernel<<<dim3(6, 512), 256, QKV_SMEM>>>(x, qw, kw, vw);
    attnqk_kernel<<<512, 256, AQK_SMEM>>>();
    corr_kernel<<<dim3(8, 64), 256, CORR_SMEM>>>();
    oproj_kernel<<<dim3(4, 512), 256, OPR_SMEM>>>(x, ow, (float*)d_out);
}